// round 1
// baseline (speedup 1.0000x reference)
#include <cuda_runtime.h>
#include <math.h>

#define EMB   1024
#define HEADS 16
#define HD    64
#define FFNDIM 4096
#define BATCH 2
#define SEQ   2048
#define NTOK  (BATCH*SEQ)

// -------- scratch (device globals; no allocation APIs allowed) --------
__device__ float g_xn [NTOK*EMB];            // ln1 output (also residual base)
__device__ float g_q  [NTOK*EMB];            // [B,H,T,D]
__device__ float g_k  [NTOK*EMB];
__device__ float g_v  [NTOK*EMB];
__device__ float g_att[NTOK*EMB];            // attention output, token-major [M,C]
__device__ float g_x2 [NTOK*EMB];            // x after attn residual
__device__ float g_h2 [NTOK*EMB];            // ln2 output
__device__ float g_hf [(size_t)NTOK*FFNDIM]; // gelu(h@W1+b1)

// ------------------------- LayerNorm --------------------------------
__global__ void __launch_bounds__(256) ln_kernel(
    const float* __restrict__ x, const float* __restrict__ g,
    const float* __restrict__ b, float* __restrict__ out)
{
    int row = blockIdx.x;
    const float* xr = x + (size_t)row * EMB;
    int t = threadIdx.x;
    float v[4];
    float s = 0.f, sq = 0.f;
#pragma unroll
    for (int i = 0; i < 4; i++) {
        v[i] = xr[t + i*256];
        s += v[i]; sq += v[i]*v[i];
    }
    __shared__ float red[2][8];
#pragma unroll
    for (int o = 16; o; o >>= 1) {
        s  += __shfl_xor_sync(0xffffffffu, s,  o);
        sq += __shfl_xor_sync(0xffffffffu, sq, o);
    }
    int w = t >> 5;
    if ((t & 31) == 0) { red[0][w] = s; red[1][w] = sq; }
    __syncthreads();
    s = red[0][t & 7]; sq = red[1][t & 7];
#pragma unroll
    for (int o = 4; o; o >>= 1) {
        s  += __shfl_xor_sync(0xffffffffu, s,  o);
        sq += __shfl_xor_sync(0xffffffffu, sq, o);
    }
    float mu   = s * (1.0f/EMB);
    float var  = sq * (1.0f/EMB) - mu*mu;
    float rstd = rsqrtf(var + 1e-5f);
    float* outr = out + (size_t)row * EMB;
#pragma unroll
    for (int i = 0; i < 4; i++) {
        int c = t + i*256;
        outr[c] = (v[i] - mu) * rstd * g[c] + b[c];
    }
}

// ------------------------- SGEMM ------------------------------------
// C[M,N] = epilogue(A[M,K] @ B[K,N] + bias), tiles 128x128x8, 8x8/thread.
// EPI 0: bias, write permuted [B,H,T,D] (for Q/K/V)
// EPI 1: bias + residual (res is [M,N] token-major)
// EPI 2: bias + exact-erf GELU
template<int EPI>
__global__ void __launch_bounds__(256) gemm_kernel(
    const float* __restrict__ A, const float* __restrict__ B,
    const float* __restrict__ bias, const float* __restrict__ res,
    float* __restrict__ C, int M, int N, int K)
{
    __shared__ float As[8*132];   // transposed A tile [k][m], pad 132
    __shared__ float Bs[8*128];   // [k][n]
    int tid = threadIdx.x;
    int m0 = blockIdx.y * 128, n0 = blockIdx.x * 128;
    int arow = tid >> 1,  acol = (tid & 1) * 4;
    int brow = tid >> 5,  bcol = (tid & 31) * 4;
    const float* Aptr = A + (size_t)(m0 + arow) * K + acol;
    const float* Bptr = B + (size_t)brow * N + n0 + bcol;
    int rbase = (tid >> 4) * 8, cbase = (tid & 15) * 8;
    float acc[8][8];
#pragma unroll
    for (int i = 0; i < 8; i++)
#pragma unroll
        for (int j = 0; j < 8; j++) acc[i][j] = 0.f;

    for (int kt = 0; kt < K; kt += 8) {
        float4 av = *(const float4*)Aptr;
        float4 bv = *(const float4*)Bptr;
        As[(acol+0)*132 + arow] = av.x;
        As[(acol+1)*132 + arow] = av.y;
        As[(acol+2)*132 + arow] = av.z;
        As[(acol+3)*132 + arow] = av.w;
        *(float4*)&Bs[brow*128 + bcol] = bv;
        __syncthreads();
#pragma unroll
        for (int kk = 0; kk < 8; kk++) {
            float4 a0 = *(float4*)&As[kk*132 + rbase];
            float4 a1 = *(float4*)&As[kk*132 + rbase + 4];
            float4 b0 = *(float4*)&Bs[kk*128 + cbase];
            float4 b1 = *(float4*)&Bs[kk*128 + cbase + 4];
            float ar[8] = {a0.x,a0.y,a0.z,a0.w,a1.x,a1.y,a1.z,a1.w};
            float br[8] = {b0.x,b0.y,b0.z,b0.w,b1.x,b1.y,b1.z,b1.w};
#pragma unroll
            for (int i = 0; i < 8; i++)
#pragma unroll
                for (int j = 0; j < 8; j++)
                    acc[i][j] += ar[i] * br[j];
        }
        __syncthreads();
        Aptr += 8;
        Bptr += (size_t)8 * N;
    }

#pragma unroll
    for (int i = 0; i < 8; i++) {
        int m = m0 + rbase + i;
#pragma unroll
        for (int j4 = 0; j4 < 8; j4 += 4) {
            int n = n0 + cbase + j4;
            float4 val;
            val.x = acc[i][j4+0] + bias[n+0];
            val.y = acc[i][j4+1] + bias[n+1];
            val.z = acc[i][j4+2] + bias[n+2];
            val.w = acc[i][j4+3] + bias[n+3];
            if (EPI == 0) {
                int bb = m >> 11, tt = m & (SEQ-1);
                int hh = n >> 6,  dd = n & (HD-1);
                size_t off = (((size_t)(bb*HEADS + hh))*SEQ + tt)*HD + dd;
                *(float4*)&C[off] = val;
            } else if (EPI == 1) {
                const float4 rv = *(const float4*)&res[(size_t)m*N + n];
                val.x += rv.x; val.y += rv.y; val.z += rv.z; val.w += rv.w;
                *(float4*)&C[(size_t)m*N + n] = val;
            } else { // GELU exact (erf)
                val.x = 0.5f*val.x*(1.0f + erff(val.x*0.70710678118654752f));
                val.y = 0.5f*val.y*(1.0f + erff(val.y*0.70710678118654752f));
                val.z = 0.5f*val.z*(1.0f + erff(val.z*0.70710678118654752f));
                val.w = 0.5f*val.w*(1.0f + erff(val.w*0.70710678118654752f));
                *(float4*)&C[(size_t)m*N + n] = val;
            }
        }
    }
}

// ------------------------- Attention --------------------------------
// Flash-style: 64 queries/block, sweep keys in 64-wide tiles, online softmax.
#define PAD 68
__global__ void __launch_bounds__(256) attn_kernel(
    const float* __restrict__ Q, const float* __restrict__ K,
    const float* __restrict__ V, float* __restrict__ O)
{
    extern __shared__ float sm[];
    float* Qs = sm;               // [d][i] transposed, pad
    float* Ks = sm + 64*PAD;      // [d][j] transposed
    float* Vs = sm + 2*64*PAD;    // [c][d]
    float* Ps = sm + 3*64*PAD;    // [c][i] transposed

    int tid = threadIdx.x;
    int tx = tid & 15, ty = tid >> 4;
    int h = blockIdx.y, b = blockIdx.z;
    int qi0 = blockIdx.x * 64;
    const float* qbase = Q + ((size_t)(b*HEADS + h))*SEQ*HD;
    const float* kbase = K + ((size_t)(b*HEADS + h))*SEQ*HD;
    const float* vbase = V + ((size_t)(b*HEADS + h))*SEQ*HD;

    // load Q tile, transposed + pre-scaled by 1/sqrt(D)
#pragma unroll
    for (int l = 0; l < 4; l++) {
        int e = tid + l*256;
        int r = e >> 4;
        int dg = (e & 15) * 4;
        float4 qv = *(const float4*)(qbase + (size_t)(qi0 + r)*HD + dg);
        Qs[(dg+0)*PAD + r] = qv.x * 0.125f;
        Qs[(dg+1)*PAD + r] = qv.y * 0.125f;
        Qs[(dg+2)*PAD + r] = qv.z * 0.125f;
        Qs[(dg+3)*PAD + r] = qv.w * 0.125f;
    }

    float m_[4], l_[4], o_[4][4];
#pragma unroll
    for (int r = 0; r < 4; r++) {
        m_[r] = -1e30f; l_[r] = 0.f;
#pragma unroll
        for (int j = 0; j < 4; j++) o_[r][j] = 0.f;
    }

    for (int s0 = 0; s0 < SEQ; s0 += 64) {
        __syncthreads();
#pragma unroll
        for (int l = 0; l < 4; l++) {
            int e = tid + l*256;
            int r = e >> 4;
            int dg = (e & 15) * 4;
            float4 kv = *(const float4*)(kbase + (size_t)(s0 + r)*HD + dg);
            Ks[(dg+0)*PAD + r] = kv.x;
            Ks[(dg+1)*PAD + r] = kv.y;
            Ks[(dg+2)*PAD + r] = kv.z;
            Ks[(dg+3)*PAD + r] = kv.w;
            float4 vv = *(const float4*)(vbase + (size_t)(s0 + r)*HD + dg);
            *(float4*)&Vs[r*PAD + dg] = vv;
        }
        __syncthreads();

        // S = Q Kt  (4x4 per thread)
        float s[4][4];
#pragma unroll
        for (int i = 0; i < 4; i++)
#pragma unroll
            for (int j = 0; j < 4; j++) s[i][j] = 0.f;
#pragma unroll 16
        for (int kk = 0; kk < 64; kk++) {
            float4 qv = *(float4*)&Qs[kk*PAD + ty*4];
            float4 kv = *(float4*)&Ks[kk*PAD + tx*4];
            float qa[4] = {qv.x,qv.y,qv.z,qv.w};
            float ka[4] = {kv.x,kv.y,kv.z,kv.w};
#pragma unroll
            for (int i = 0; i < 4; i++)
#pragma unroll
                for (int j = 0; j < 4; j++)
                    s[i][j] += qa[i]*ka[j];
        }

        // online softmax per query row (rows owned by ty group, reduce over tx)
#pragma unroll
        for (int r = 0; r < 4; r++) {
            float mx = fmaxf(fmaxf(s[r][0], s[r][1]), fmaxf(s[r][2], s[r][3]));
#pragma unroll
            for (int o2 = 8; o2; o2 >>= 1)
                mx = fmaxf(mx, __shfl_xor_sync(0xffffffffu, mx, o2, 16));
            float nm = fmaxf(m_[r], mx);
            float cf = __expf(m_[r] - nm);
            float p[4], ps = 0.f;
#pragma unroll
            for (int c = 0; c < 4; c++) { p[c] = __expf(s[r][c] - nm); ps += p[c]; }
#pragma unroll
            for (int o2 = 8; o2; o2 >>= 1)
                ps += __shfl_xor_sync(0xffffffffu, ps, o2, 16);
            l_[r] = l_[r]*cf + ps;
            m_[r] = nm;
#pragma unroll
            for (int j = 0; j < 4; j++) o_[r][j] *= cf;
#pragma unroll
            for (int c = 0; c < 4; c++)
                Ps[(tx*4 + c)*PAD + ty*4 + r] = p[c];
        }
        __syncthreads();

        // O += P V  (inner dim = 64 keys)
#pragma unroll 16
        for (int c = 0; c < 64; c++) {
            float4 pv = *(float4*)&Ps[c*PAD + ty*4];
            float4 vv = *(float4*)&Vs[c*PAD + tx*4];
            float pa[4] = {pv.x,pv.y,pv.z,pv.w};
            float va[4] = {vv.x,vv.y,vv.z,vv.w};
#pragma unroll
            for (int i = 0; i < 4; i++)
#pragma unroll
                for (int j = 0; j < 4; j++)
                    o_[i][j] += pa[i]*va[j];
        }
    }

    // finalize + write token-major [M, C]
#pragma unroll
    for (int r = 0; r < 4; r++) {
        float inv = 1.0f / l_[r];
        int t = qi0 + ty*4 + r;
        float4 ov;
        ov.x = o_[r][0]*inv; ov.y = o_[r][1]*inv;
        ov.z = o_[r][2]*inv; ov.w = o_[r][3]*inv;
        *(float4*)&O[((size_t)(b*SEQ + t))*EMB + h*HD + tx*4] = ov;
    }
}

// ------------------------- launch -----------------------------------
extern "C" void kernel_launch(void* const* d_in, const int* in_sizes, int n_in,
                              void* d_out, int out_size)
{
    const float* x     = (const float*)d_in[0];
    const float* ln1_g = (const float*)d_in[2];
    const float* ln1_b = (const float*)d_in[3];
    const float* ln2_g = (const float*)d_in[4];
    const float* ln2_b = (const float*)d_in[5];
    const float* Wq = (const float*)d_in[6];
    const float* bq = (const float*)d_in[7];
    const float* Wk = (const float*)d_in[8];
    const float* bk = (const float*)d_in[9];
    const float* Wv = (const float*)d_in[10];
    const float* bv = (const float*)d_in[11];
    const float* Wo = (const float*)d_in[12];
    const float* bo = (const float*)d_in[13];
    const float* W1 = (const float*)d_in[14];
    const float* b1 = (const float*)d_in[15];
    const float* W2 = (const float*)d_in[16];
    const float* b2 = (const float*)d_in[17];

    float *xn, *q, *k, *v, *att, *x2, *h2, *hf;
    cudaGetSymbolAddress((void**)&xn,  g_xn);
    cudaGetSymbolAddress((void**)&q,   g_q);
    cudaGetSymbolAddress((void**)&k,   g_k);
    cudaGetSymbolAddress((void**)&v,   g_v);
    cudaGetSymbolAddress((void**)&att, g_att);
    cudaGetSymbolAddress((void**)&x2,  g_x2);
    cudaGetSymbolAddress((void**)&h2,  g_h2);
    cudaGetSymbolAddress((void**)&hf,  g_hf);

    const int ATT_SMEM = 4*64*PAD*sizeof(float); // 69632 B
    cudaFuncSetAttribute(attn_kernel, cudaFuncAttributeMaxDynamicSharedMemorySize, ATT_SMEM);

    // ln1
    ln_kernel<<<NTOK, 256>>>(x, ln1_g, ln1_b, xn);
    // QKV projections -> [B,H,T,D]
    gemm_kernel<0><<<dim3(EMB/128, NTOK/128), 256>>>(xn, Wq, bq, nullptr, q, NTOK, EMB, EMB);
    gemm_kernel<0><<<dim3(EMB/128, NTOK/128), 256>>>(xn, Wk, bk, nullptr, k, NTOK, EMB, EMB);
    gemm_kernel<0><<<dim3(EMB/128, NTOK/128), 256>>>(xn, Wv, bv, nullptr, v, NTOK, EMB, EMB);
    // attention
    attn_kernel<<<dim3(SEQ/64, HEADS, BATCH), 256, ATT_SMEM>>>(q, k, v, att);
    // output projection + residual (residual = ln1 output per reference)
    gemm_kernel<1><<<dim3(EMB/128, NTOK/128), 256>>>(att, Wo, bo, xn, x2, NTOK, EMB, EMB);
    // ln2
    ln_kernel<<<NTOK, 256>>>(x2, ln2_g, ln2_b, h2);
    // FFN
    gemm_kernel<2><<<dim3(FFNDIM/128, NTOK/128), 256>>>(h2, W1, b1, nullptr, hf, NTOK, FFNDIM, EMB);
    gemm_kernel<1><<<dim3(EMB/128, NTOK/128), 256>>>(hf, W2, b2, x2, (float*)d_out, NTOK, EMB, FFNDIM);
}

// round 3
// speedup vs baseline: 1.0324x; 1.0324x over previous
#include <cuda_runtime.h>
#include <math.h>

#define EMB   1024
#define HEADS 16
#define HD    64
#define FFNDIM 4096
#define BATCH 2
#define SEQ   2048
#define NTOK  (BATCH*SEQ)

// -------- scratch (device globals; no allocation APIs allowed) --------
__device__ float g_xn [NTOK*EMB];            // ln1 output (also residual base)
__device__ float g_q  [NTOK*EMB];            // [B,H,T,D]
__device__ float g_k  [NTOK*EMB];
__device__ float g_v  [NTOK*EMB];
__device__ float g_att[NTOK*EMB];            // attention output, token-major [M,C]
__device__ float g_x2 [NTOK*EMB];            // x after attn residual
__device__ float g_h2 [NTOK*EMB];            // ln2 output
__device__ float g_hf [(size_t)NTOK*FFNDIM]; // gelu(h@W1+b1)

// ---------------- packed fp32x2 helpers (Blackwell FFMA2 path) -------
__device__ __forceinline__ void fma2(float2 &d, const float2 &a, const float2 &b) {
    asm("fma.rn.f32x2 %0, %1, %2, %0;"
        : "+l"(reinterpret_cast<unsigned long long&>(d))
        : "l"(reinterpret_cast<const unsigned long long&>(a)),
          "l"(reinterpret_cast<const unsigned long long&>(b)));
}
__device__ __forceinline__ float2 dup2(float x) {
    float2 r;
    asm("mov.b64 %0, {%1, %1};"
        : "=l"(reinterpret_cast<unsigned long long&>(r)) : "f"(x));
    return r;
}

// ------------------------- LayerNorm --------------------------------
__global__ void __launch_bounds__(256) ln_kernel(
    const float* __restrict__ x, const float* __restrict__ g,
    const float* __restrict__ b, float* __restrict__ out)
{
    int row = blockIdx.x;
    const float* xr = x + (size_t)row * EMB;
    int t = threadIdx.x;
    float v[4];
    float s = 0.f, sq = 0.f;
#pragma unroll
    for (int i = 0; i < 4; i++) {
        v[i] = xr[t + i*256];
        s += v[i]; sq += v[i]*v[i];
    }
    __shared__ float red[2][8];
#pragma unroll
    for (int o = 16; o; o >>= 1) {
        s  += __shfl_xor_sync(0xffffffffu, s,  o);
        sq += __shfl_xor_sync(0xffffffffu, sq, o);
    }
    int w = t >> 5;
    if ((t & 31) == 0) { red[0][w] = s; red[1][w] = sq; }
    __syncthreads();
    s = red[0][t & 7]; sq = red[1][t & 7];
#pragma unroll
    for (int o = 4; o; o >>= 1) {
        s  += __shfl_xor_sync(0xffffffffu, s,  o);
        sq += __shfl_xor_sync(0xffffffffu, sq, o);
    }
    float mu   = s * (1.0f/EMB);
    float var  = sq * (1.0f/EMB) - mu*mu;
    float rstd = rsqrtf(var + 1e-5f);
    float* outr = out + (size_t)row * EMB;
#pragma unroll
    for (int i = 0; i < 4; i++) {
        int c = t + i*256;
        outr[c] = (v[i] - mu) * rstd * g[c] + b[c];
    }
}

// ------------------------- SGEMM ------------------------------------
// C[M,N] = epilogue(A[M,K] @ B[K,N] + bias), tiles 128x128x8, 8x8/thread,
// f32x2 packed accumulators (pairs along N), double-buffered smem.
// EPI 0: bias, write permuted [B,H,T,D] (for Q/K/V)
// EPI 1: bias + residual (res is [M,N] token-major)
// EPI 2: bias + exact-erf GELU
template<int EPI>
__global__ void __launch_bounds__(256) gemm_kernel(
    const float* __restrict__ A, const float* __restrict__ B,
    const float* __restrict__ bias, const float* __restrict__ res,
    float* __restrict__ C, int M, int N, int K)
{
    __shared__ float As[2][8*132];   // transposed A tile [k][m], pad 132
    __shared__ float Bs[2][8*128];   // [k][n]
    int tid = threadIdx.x;
    int m0 = blockIdx.y * 128, n0 = blockIdx.x * 128;
    int arow = tid >> 1,  acol = (tid & 1) * 4;
    int brow = tid >> 5,  bcol = (tid & 31) * 4;
    const float* Aptr = A + (size_t)(m0 + arow) * K + acol;
    const float* Bptr = B + (size_t)brow * N + n0 + bcol;
    int rbase = (tid >> 4) * 8, cbase = (tid & 15) * 8;

    float2 acc[8][4];
#pragma unroll
    for (int i = 0; i < 8; i++)
#pragma unroll
        for (int j = 0; j < 4; j++) acc[i][j] = make_float2(0.f, 0.f);

    // prologue: stage tile 0
    {
        float4 av = *(const float4*)Aptr;
        float4 bv = *(const float4*)Bptr;
        As[0][(acol+0)*132 + arow] = av.x;
        As[0][(acol+1)*132 + arow] = av.y;
        As[0][(acol+2)*132 + arow] = av.z;
        As[0][(acol+3)*132 + arow] = av.w;
        *(float4*)&Bs[0][brow*128 + bcol] = bv;
    }
    __syncthreads();

    int ktiles = K >> 3;
    int cur = 0;
    for (int t = 0; t < ktiles; t++) {
        float4 av2, bv2;
        bool more = (t + 1 < ktiles);
        if (more) {
            Aptr += 8;
            Bptr += (size_t)8 * N;
            av2 = *(const float4*)Aptr;
            bv2 = *(const float4*)Bptr;
        }
#pragma unroll
        for (int kk = 0; kk < 8; kk++) {
            float4 a0 = *(float4*)&As[cur][kk*132 + rbase];
            float4 a1 = *(float4*)&As[cur][kk*132 + rbase + 4];
            float2 b0 = *(float2*)&Bs[cur][kk*128 + cbase];
            float2 b1 = *(float2*)&Bs[cur][kk*128 + cbase + 2];
            float2 b2 = *(float2*)&Bs[cur][kk*128 + cbase + 4];
            float2 b3 = *(float2*)&Bs[cur][kk*128 + cbase + 6];
            float ar[8] = {a0.x,a0.y,a0.z,a0.w,a1.x,a1.y,a1.z,a1.w};
#pragma unroll
            for (int i = 0; i < 8; i++) {
                float2 ad = dup2(ar[i]);
                fma2(acc[i][0], ad, b0);
                fma2(acc[i][1], ad, b1);
                fma2(acc[i][2], ad, b2);
                fma2(acc[i][3], ad, b3);
            }
        }
        if (more) {
            int nxt = cur ^ 1;
            As[nxt][(acol+0)*132 + arow] = av2.x;
            As[nxt][(acol+1)*132 + arow] = av2.y;
            As[nxt][(acol+2)*132 + arow] = av2.z;
            As[nxt][(acol+3)*132 + arow] = av2.w;
            *(float4*)&Bs[nxt][brow*128 + bcol] = bv2;
            __syncthreads();
            cur = nxt;
        }
    }

#pragma unroll
    for (int i = 0; i < 8; i++) {
        int m = m0 + rbase + i;
#pragma unroll
        for (int jq = 0; jq < 2; jq++) {
            int n = n0 + cbase + jq*4;
            float4 val;
            val.x = acc[i][jq*2+0].x + bias[n+0];
            val.y = acc[i][jq*2+0].y + bias[n+1];
            val.z = acc[i][jq*2+1].x + bias[n+2];
            val.w = acc[i][jq*2+1].y + bias[n+3];
            if (EPI == 0) {
                int bb = m >> 11, tt = m & (SEQ-1);
                int hh = n >> 6,  dd = n & (HD-1);
                size_t off = (((size_t)(bb*HEADS + hh))*SEQ + tt)*HD + dd;
                *(float4*)&C[off] = val;
            } else if (EPI == 1) {
                const float4 rv = *(const float4*)&res[(size_t)m*N + n];
                val.x += rv.x; val.y += rv.y; val.z += rv.z; val.w += rv.w;
                *(float4*)&C[(size_t)m*N + n] = val;
            } else { // GELU exact (erf)
                val.x = 0.5f*val.x*(1.0f + erff(val.x*0.70710678118654752f));
                val.y = 0.5f*val.y*(1.0f + erff(val.y*0.70710678118654752f));
                val.z = 0.5f*val.z*(1.0f + erff(val.z*0.70710678118654752f));
                val.w = 0.5f*val.w*(1.0f + erff(val.w*0.70710678118654752f));
                *(float4*)&C[(size_t)m*N + n] = val;
            }
        }
    }
}

// ------------------------- Attention --------------------------------
// Flash-style: 64 queries/block, sweep keys in 64-wide tiles, online softmax.
#define PAD 68
__global__ void __launch_bounds__(256) attn_kernel(
    const float* __restrict__ Q, const float* __restrict__ K,
    const float* __restrict__ V, float* __restrict__ O)
{
    extern __shared__ float sm[];
    float* Qs = sm;               // [d][i] transposed, pad
    float* Ks = sm + 64*PAD;      // [d][j] transposed
    float* Vs = sm + 2*64*PAD;    // [c][d]
    float* Ps = sm + 3*64*PAD;    // [c][i] transposed

    int tid = threadIdx.x;
    int tx = tid & 15, ty = tid >> 4;
    int h = blockIdx.y, b = blockIdx.z;
    int qi0 = blockIdx.x * 64;
    const float* qbase = Q + ((size_t)(b*HEADS + h))*SEQ*HD;
    const float* kbase = K + ((size_t)(b*HEADS + h))*SEQ*HD;
    const float* vbase = V + ((size_t)(b*HEADS + h))*SEQ*HD;

    // load Q tile, transposed + pre-scaled by 1/sqrt(D)
#pragma unroll
    for (int l = 0; l < 4; l++) {
        int e = tid + l*256;
        int r = e >> 4;
        int dg = (e & 15) * 4;
        float4 qv = *(const float4*)(qbase + (size_t)(qi0 + r)*HD + dg);
        Qs[(dg+0)*PAD + r] = qv.x * 0.125f;
        Qs[(dg+1)*PAD + r] = qv.y * 0.125f;
        Qs[(dg+2)*PAD + r] = qv.z * 0.125f;
        Qs[(dg+3)*PAD + r] = qv.w * 0.125f;
    }

    float m_[4], l_[4];
    float2 o_[4][2];
#pragma unroll
    for (int r = 0; r < 4; r++) {
        m_[r] = -1e30f; l_[r] = 0.f;
        o_[r][0] = make_float2(0.f, 0.f);
        o_[r][1] = make_float2(0.f, 0.f);
    }

    for (int s0 = 0; s0 < SEQ; s0 += 64) {
        __syncthreads();
#pragma unroll
        for (int l = 0; l < 4; l++) {
            int e = tid + l*256;
            int r = e >> 4;
            int dg = (e & 15) * 4;
            float4 kv = *(const float4*)(kbase + (size_t)(s0 + r)*HD + dg);
            Ks[(dg+0)*PAD + r] = kv.x;
            Ks[(dg+1)*PAD + r] = kv.y;
            Ks[(dg+2)*PAD + r] = kv.z;
            Ks[(dg+3)*PAD + r] = kv.w;
            float4 vv = *(const float4*)(vbase + (size_t)(s0 + r)*HD + dg);
            *(float4*)&Vs[r*PAD + dg] = vv;
        }
        __syncthreads();

        // S = Q Kt  (4x4 per thread, f32x2 pairs along key dim)
        float2 s2[4][2];
#pragma unroll
        for (int i = 0; i < 4; i++) {
            s2[i][0] = make_float2(0.f, 0.f);
            s2[i][1] = make_float2(0.f, 0.f);
        }
#pragma unroll 16
        for (int kk = 0; kk < 64; kk++) {
            float4 qv = *(float4*)&Qs[kk*PAD + ty*4];
            float2 k0 = *(float2*)&Ks[kk*PAD + tx*4];
            float2 k1 = *(float2*)&Ks[kk*PAD + tx*4 + 2];
            float qa[4] = {qv.x,qv.y,qv.z,qv.w};
#pragma unroll
            for (int i = 0; i < 4; i++) {
                float2 qd = dup2(qa[i]);
                fma2(s2[i][0], qd, k0);
                fma2(s2[i][1], qd, k1);
            }
        }

        // online softmax per query row (rows owned by ty group, reduce over tx)
#pragma unroll
        for (int r = 0; r < 4; r++) {
            float sv[4] = {s2[r][0].x, s2[r][0].y, s2[r][1].x, s2[r][1].y};
            float mx = fmaxf(fmaxf(sv[0], sv[1]), fmaxf(sv[2], sv[3]));
#pragma unroll
            for (int o2 = 8; o2; o2 >>= 1)
                mx = fmaxf(mx, __shfl_xor_sync(0xffffffffu, mx, o2, 16));
            float nm = fmaxf(m_[r], mx);
            float cf = __expf(m_[r] - nm);
            float p[4], ps = 0.f;
#pragma unroll
            for (int c = 0; c < 4; c++) { p[c] = __expf(sv[c] - nm); ps += p[c]; }
#pragma unroll
            for (int o2 = 8; o2; o2 >>= 1)
                ps += __shfl_xor_sync(0xffffffffu, ps, o2, 16);
            l_[r] = l_[r]*cf + ps;
            m_[r] = nm;
            o_[r][0].x *= cf; o_[r][0].y *= cf;
            o_[r][1].x *= cf; o_[r][1].y *= cf;
#pragma unroll
            for (int c = 0; c < 4; c++)
                Ps[(tx*4 + c)*PAD + ty*4 + r] = p[c];
        }
        __syncthreads();

        // O += P V  (inner dim = 64 keys, f32x2 pairs along headdim)
#pragma unroll 16
        for (int c = 0; c < 64; c++) {
            float4 pv = *(float4*)&Ps[c*PAD + ty*4];
            float2 v0 = *(float2*)&Vs[c*PAD + tx*4];
            float2 v1 = *(float2*)&Vs[c*PAD + tx*4 + 2];
            float pa[4] = {pv.x,pv.y,pv.z,pv.w};
#pragma unroll
            for (int i = 0; i < 4; i++) {
                float2 pd = dup2(pa[i]);
                fma2(o_[i][0], pd, v0);
                fma2(o_[i][1], pd, v1);
            }
        }
    }

    // finalize + write token-major [M, C]
#pragma unroll
    for (int r = 0; r < 4; r++) {
        float inv = 1.0f / l_[r];
        int t = qi0 + ty*4 + r;
        float4 ov;
        ov.x = o_[r][0].x*inv; ov.y = o_[r][0].y*inv;
        ov.z = o_[r][1].x*inv; ov.w = o_[r][1].y*inv;
        *(float4*)&O[((size_t)(b*SEQ + t))*EMB + h*HD + tx*4] = ov;
    }
}

// ------------------------- launch -----------------------------------
extern "C" void kernel_launch(void* const* d_in, const int* in_sizes, int n_in,
                              void* d_out, int out_size)
{
    const float* x     = (const float*)d_in[0];
    const float* ln1_g = (const float*)d_in[2];
    const float* ln1_b = (const float*)d_in[3];
    const float* ln2_g = (const float*)d_in[4];
    const float* ln2_b = (const float*)d_in[5];
    const float* Wq = (const float*)d_in[6];
    const float* bq = (const float*)d_in[7];
    const float* Wk = (const float*)d_in[8];
    const float* bk = (const float*)d_in[9];
    const float* Wv = (const float*)d_in[10];
    const float* bv = (const float*)d_in[11];
    const float* Wo = (const float*)d_in[12];
    const float* bo = (const float*)d_in[13];
    const float* W1 = (const float*)d_in[14];
    const float* b1 = (const float*)d_in[15];
    const float* W2 = (const float*)d_in[16];
    const float* b2 = (const float*)d_in[17];

    float *xn, *q, *k, *v, *att, *x2, *h2, *hf;
    cudaGetSymbolAddress((void**)&xn,  g_xn);
    cudaGetSymbolAddress((void**)&q,   g_q);
    cudaGetSymbolAddress((void**)&k,   g_k);
    cudaGetSymbolAddress((void**)&v,   g_v);
    cudaGetSymbolAddress((void**)&att, g_att);
    cudaGetSymbolAddress((void**)&x2,  g_x2);
    cudaGetSymbolAddress((void**)&h2,  g_h2);
    cudaGetSymbolAddress((void**)&hf,  g_hf);

    const int ATT_SMEM = 4*64*PAD*sizeof(float); // 69632 B
    cudaFuncSetAttribute(attn_kernel, cudaFuncAttributeMaxDynamicSharedMemorySize, ATT_SMEM);

    // ln1
    ln_kernel<<<NTOK, 256>>>(x, ln1_g, ln1_b, xn);
    // QKV projections -> [B,H,T,D]
    gemm_kernel<0><<<dim3(EMB/128, NTOK/128), 256>>>(xn, Wq, bq, nullptr, q, NTOK, EMB, EMB);
    gemm_kernel<0><<<dim3(EMB/128, NTOK/128), 256>>>(xn, Wk, bk, nullptr, k, NTOK, EMB, EMB);
    gemm_kernel<0><<<dim3(EMB/128, NTOK/128), 256>>>(xn, Wv, bv, nullptr, v, NTOK, EMB, EMB);
    // attention
    attn_kernel<<<dim3(SEQ/64, HEADS, BATCH), 256, ATT_SMEM>>>(q, k, v, att);
    // output projection + residual (residual = ln1 output per reference)
    gemm_kernel<1><<<dim3(EMB/128, NTOK/128), 256>>>(att, Wo, bo, xn, x2, NTOK, EMB, EMB);
    // ln2
    ln_kernel<<<NTOK, 256>>>(x2, ln2_g, ln2_b, h2);
    // FFN
    gemm_kernel<2><<<dim3(FFNDIM/128, NTOK/128), 256>>>(h2, W1, b1, nullptr, hf, NTOK, FFNDIM, EMB);
    gemm_kernel<1><<<dim3(EMB/128, NTOK/128), 256>>>(hf, W2, b2, x2, (float*)d_out, NTOK, EMB, FFNDIM);
}

// round 6
// speedup vs baseline: 1.2541x; 1.2147x over previous
#include <cuda_runtime.h>
#include <math.h>

#define EMB   1024
#define HEADS 16
#define HD    64
#define FFNDIM 4096
#define BATCH 2
#define SEQ   2048
#define NTOK  (BATCH*SEQ)

// -------- scratch (device globals; no allocation APIs allowed) --------
__device__ float g_xn [NTOK*EMB];            // ln1 output (also residual base)
__device__ float g_q  [NTOK*EMB];            // [B,H,T,D]
__device__ float g_k  [NTOK*EMB];
__device__ float g_v  [NTOK*EMB];
__device__ float g_att[NTOK*EMB];            // attention output, token-major [M,C]
__device__ float g_x2 [NTOK*EMB];            // x after attn residual
__device__ float g_h2 [NTOK*EMB];            // ln2 output
__device__ float g_hf [(size_t)NTOK*FFNDIM]; // gelu(h@W1+b1)

// ---------------- packed fp32x2 helpers (Blackwell FFMA2 path) -------
__device__ __forceinline__ void fma2(float2 &d, const float2 &a, const float2 &b) {
    asm("fma.rn.f32x2 %0, %1, %2, %0;"
        : "+l"(reinterpret_cast<unsigned long long&>(d))
        : "l"(reinterpret_cast<const unsigned long long&>(a)),
          "l"(reinterpret_cast<const unsigned long long&>(b)));
}
__device__ __forceinline__ float2 dup2(float x) {
    float2 r;
    asm("mov.b64 %0, {%1, %1};"
        : "=l"(reinterpret_cast<unsigned long long&>(r)) : "f"(x));
    return r;
}

// ------------------------- LayerNorm --------------------------------
__global__ void __launch_bounds__(256) ln_kernel(
    const float* __restrict__ x, const float* __restrict__ g,
    const float* __restrict__ b, float* __restrict__ out)
{
    int row = blockIdx.x;
    const float* xr = x + (size_t)row * EMB;
    int t = threadIdx.x;
    float v[4];
    float s = 0.f, sq = 0.f;
#pragma unroll
    for (int i = 0; i < 4; i++) {
        v[i] = xr[t + i*256];
        s += v[i]; sq += v[i]*v[i];
    }
    __shared__ float red[2][8];
#pragma unroll
    for (int o = 16; o; o >>= 1) {
        s  += __shfl_xor_sync(0xffffffffu, s,  o);
        sq += __shfl_xor_sync(0xffffffffu, sq, o);
    }
    int w = t >> 5;
    if ((t & 31) == 0) { red[0][w] = s; red[1][w] = sq; }
    __syncthreads();
    s = red[0][t & 7]; sq = red[1][t & 7];
#pragma unroll
    for (int o = 4; o; o >>= 1) {
        s  += __shfl_xor_sync(0xffffffffu, s,  o);
        sq += __shfl_xor_sync(0xffffffffu, sq, o);
    }
    float mu   = s * (1.0f/EMB);
    float var  = sq * (1.0f/EMB) - mu*mu;
    float rstd = rsqrtf(var + 1e-5f);
    float* outr = out + (size_t)row * EMB;
#pragma unroll
    for (int i = 0; i < 4; i++) {
        int c = t + i*256;
        outr[c] = (v[i] - mu) * rstd * g[c] + b[c];
    }
}

// ------------------------- SGEMM ------------------------------------
// C[M,N] = epilogue(A[M,K] @ B[K,N] + bias), tiles 128x128x8, 8x8/thread,
// f32x2 packed accumulators. B-fragment mapping: thread (txg=tid&15) owns
// column pairs {2txg+32c, 2txg+1+32c}, c=0..3 -> conflict-free LDS.64.
// EPI 0: bias, write permuted [B,H,T,D] (for Q/K/V)
// EPI 1: bias + residual (res is [M,N] token-major)
// EPI 2: bias + exact-erf GELU
template<int EPI>
__global__ void __launch_bounds__(256, 2) gemm_kernel(
    const float* __restrict__ A, const float* __restrict__ B,
    const float* __restrict__ bias, const float* __restrict__ res,
    float* __restrict__ C, int M, int N, int K)
{
    __shared__ float As[2][8*132];   // transposed A tile [k][m], pad 132
    __shared__ float Bs[2][8*128];   // [k][n]
    int tid = threadIdx.x;
    int m0 = blockIdx.y * 128, n0 = blockIdx.x * 128;
    int arow = tid >> 1,  acol = (tid & 1) * 4;
    int brow = tid >> 5,  bcol = (tid & 31) * 4;
    const float* Aptr = A + (size_t)(m0 + arow) * K + acol;
    const float* Bptr = B + (size_t)brow * N + n0 + bcol;
    int rbase = (tid >> 4) * 8;
    int txg   = tid & 15;            // column-group owner

    float2 acc[8][4];
#pragma unroll
    for (int i = 0; i < 8; i++)
#pragma unroll
        for (int j = 0; j < 4; j++) acc[i][j] = make_float2(0.f, 0.f);

    // prologue: stage tile 0
    {
        float4 av = *(const float4*)Aptr;
        float4 bv = *(const float4*)Bptr;
        As[0][(acol+0)*132 + arow] = av.x;
        As[0][(acol+1)*132 + arow] = av.y;
        As[0][(acol+2)*132 + arow] = av.z;
        As[0][(acol+3)*132 + arow] = av.w;
        *(float4*)&Bs[0][brow*128 + bcol] = bv;
    }
    __syncthreads();

    int ktiles = K >> 3;
    int cur = 0;
    for (int t = 0; t < ktiles; t++) {
        float4 av2, bv2;
        bool more = (t + 1 < ktiles);
        if (more) {
            Aptr += 8;
            Bptr += (size_t)8 * N;
            av2 = *(const float4*)Aptr;
            bv2 = *(const float4*)Bptr;
        }
#pragma unroll
        for (int kk = 0; kk < 8; kk++) {
            float4 a0 = *(float4*)&As[cur][kk*132 + rbase];
            float4 a1 = *(float4*)&As[cur][kk*132 + rbase + 4];
            float2 b0 = *(float2*)&Bs[cur][kk*128 + 2*txg];
            float2 b1 = *(float2*)&Bs[cur][kk*128 + 2*txg + 32];
            float2 b2 = *(float2*)&Bs[cur][kk*128 + 2*txg + 64];
            float2 b3 = *(float2*)&Bs[cur][kk*128 + 2*txg + 96];
            float ar[8] = {a0.x,a0.y,a0.z,a0.w,a1.x,a1.y,a1.z,a1.w};
#pragma unroll
            for (int i = 0; i < 8; i++) {
                float2 ad = dup2(ar[i]);
                fma2(acc[i][0], ad, b0);
                fma2(acc[i][1], ad, b1);
                fma2(acc[i][2], ad, b2);
                fma2(acc[i][3], ad, b3);
            }
        }
        if (more) {
            int nxt = cur ^ 1;
            As[nxt][(acol+0)*132 + arow] = av2.x;
            As[nxt][(acol+1)*132 + arow] = av2.y;
            As[nxt][(acol+2)*132 + arow] = av2.z;
            As[nxt][(acol+3)*132 + arow] = av2.w;
            *(float4*)&Bs[nxt][brow*128 + bcol] = bv2;
            __syncthreads();
            cur = nxt;
        }
    }

#pragma unroll
    for (int i = 0; i < 8; i++) {
        int m = m0 + rbase + i;
#pragma unroll
        for (int c = 0; c < 4; c++) {
            int n = n0 + 2*txg + 32*c;
            float2 val;
            val.x = acc[i][c].x + bias[n+0];
            val.y = acc[i][c].y + bias[n+1];
            if (EPI == 0) {
                int bb = m >> 11, tt = m & (SEQ-1);
                int hh = n >> 6,  dd = n & (HD-1);
                size_t off = (((size_t)(bb*HEADS + hh))*SEQ + tt)*HD + dd;
                *(float2*)&C[off] = val;
            } else if (EPI == 1) {
                const float2 rv = *(const float2*)&res[(size_t)m*N + n];
                val.x += rv.x; val.y += rv.y;
                *(float2*)&C[(size_t)m*N + n] = val;
            } else { // GELU exact (erf)
                val.x = 0.5f*val.x*(1.0f + erff(val.x*0.70710678118654752f));
                val.y = 0.5f*val.y*(1.0f + erff(val.y*0.70710678118654752f));
                *(float2*)&C[(size_t)m*N + n] = val;
            }
        }
    }
}

// ------------------------- Attention --------------------------------
// Flash-style: 64 queries/block, sweep keys in 64-wide tiles, online softmax.
// Key/headdim fragment: thread tx owns {2tx, 2tx+1, 2tx+32, 2tx+33} -> LDS.64
// pairs span all 32 banks, conflict-free. PAD must be a multiple of 4 so
// every kk*PAD row base keeps float4/float2 accesses 16B/8B-aligned.
#define PAD 68
__global__ void __launch_bounds__(256) attn_kernel(
    const float* __restrict__ Q, const float* __restrict__ K,
    const float* __restrict__ V, float* __restrict__ O)
{
    extern __shared__ float sm[];
    float* Qs = sm;               // [d][i] transposed, pad
    float* Ks = sm + 64*PAD;      // [d][j] transposed
    float* Vs = sm + 2*64*PAD;    // [c][d]
    float* Ps = sm + 3*64*PAD;    // [c][i] transposed

    int tid = threadIdx.x;
    int tx = tid & 15, ty = tid >> 4;
    int h = blockIdx.y, b = blockIdx.z;
    int qi0 = blockIdx.x * 64;
    const float* qbase = Q + ((size_t)(b*HEADS + h))*SEQ*HD;
    const float* kbase = K + ((size_t)(b*HEADS + h))*SEQ*HD;
    const float* vbase = V + ((size_t)(b*HEADS + h))*SEQ*HD;

    // load Q tile, transposed + pre-scaled by 1/sqrt(D)
#pragma unroll
    for (int l = 0; l < 4; l++) {
        int e = tid + l*256;
        int r = e >> 4;
        int dg = (e & 15) * 4;
        float4 qv = *(const float4*)(qbase + (size_t)(qi0 + r)*HD + dg);
        Qs[(dg+0)*PAD + r] = qv.x * 0.125f;
        Qs[(dg+1)*PAD + r] = qv.y * 0.125f;
        Qs[(dg+2)*PAD + r] = qv.z * 0.125f;
        Qs[(dg+3)*PAD + r] = qv.w * 0.125f;
    }

    float m_[4], l_[4];
    float2 o_[4][2];
#pragma unroll
    for (int r = 0; r < 4; r++) {
        m_[r] = -1e30f; l_[r] = 0.f;
        o_[r][0] = make_float2(0.f, 0.f);
        o_[r][1] = make_float2(0.f, 0.f);
    }

    for (int s0 = 0; s0 < SEQ; s0 += 64) {
        __syncthreads();
#pragma unroll
        for (int l = 0; l < 4; l++) {
            int e = tid + l*256;
            int r = e >> 4;
            int dg = (e & 15) * 4;
            float4 kv = *(const float4*)(kbase + (size_t)(s0 + r)*HD + dg);
            Ks[(dg+0)*PAD + r] = kv.x;
            Ks[(dg+1)*PAD + r] = kv.y;
            Ks[(dg+2)*PAD + r] = kv.z;
            Ks[(dg+3)*PAD + r] = kv.w;
            float4 vv = *(const float4*)(vbase + (size_t)(s0 + r)*HD + dg);
            *(float4*)&Vs[r*PAD + dg] = vv;
        }
        __syncthreads();

        // S = Q Kt  (keys {2tx,2tx+1} and {2tx+32,2tx+33} per thread)
        float2 s2[4][2];
#pragma unroll
        for (int i = 0; i < 4; i++) {
            s2[i][0] = make_float2(0.f, 0.f);
            s2[i][1] = make_float2(0.f, 0.f);
        }
#pragma unroll 16
        for (int kk = 0; kk < 64; kk++) {
            float4 qv = *(float4*)&Qs[kk*PAD + ty*4];
            float2 k0 = *(float2*)&Ks[kk*PAD + 2*tx];
            float2 k1 = *(float2*)&Ks[kk*PAD + 2*tx + 32];
            float qa[4] = {qv.x,qv.y,qv.z,qv.w};
#pragma unroll
            for (int i = 0; i < 4; i++) {
                float2 qd = dup2(qa[i]);
                fma2(s2[i][0], qd, k0);
                fma2(s2[i][1], qd, k1);
            }
        }

        // online softmax per query row (rows owned by ty group, reduce over tx)
#pragma unroll
        for (int r = 0; r < 4; r++) {
            float sv[4] = {s2[r][0].x, s2[r][0].y, s2[r][1].x, s2[r][1].y};
            float mx = fmaxf(fmaxf(sv[0], sv[1]), fmaxf(sv[2], sv[3]));
#pragma unroll
            for (int o2 = 8; o2; o2 >>= 1)
                mx = fmaxf(mx, __shfl_xor_sync(0xffffffffu, mx, o2, 16));
            float nm = fmaxf(m_[r], mx);
            float cf = __expf(m_[r] - nm);
            float p[4], ps = 0.f;
#pragma unroll
            for (int c = 0; c < 4; c++) { p[c] = __expf(sv[c] - nm); ps += p[c]; }
#pragma unroll
            for (int o2 = 8; o2; o2 >>= 1)
                ps += __shfl_xor_sync(0xffffffffu, ps, o2, 16);
            l_[r] = l_[r]*cf + ps;
            m_[r] = nm;
            o_[r][0].x *= cf; o_[r][0].y *= cf;
            o_[r][1].x *= cf; o_[r][1].y *= cf;
#pragma unroll
            for (int c = 0; c < 4; c++) {
                int j = 2*tx + (c & 1) + (c >> 1)*32;
                Ps[j*PAD + ty*4 + r] = p[c];
            }
        }
        __syncthreads();

        // O += P V  (inner dim = 64 keys; headdim pairs {2tx},{2tx+32})
#pragma unroll 16
        for (int c = 0; c < 64; c++) {
            float4 pv = *(float4*)&Ps[c*PAD + ty*4];
            float2 v0 = *(float2*)&Vs[c*PAD + 2*tx];
            float2 v1 = *(float2*)&Vs[c*PAD + 2*tx + 32];
            float pa[4] = {pv.x,pv.y,pv.z,pv.w};
#pragma unroll
            for (int i = 0; i < 4; i++) {
                float2 pd = dup2(pa[i]);
                fma2(o_[i][0], pd, v0);
                fma2(o_[i][1], pd, v1);
            }
        }
    }

    // finalize + write token-major [M, C]; cols {2tx, 2tx+32} pairs
#pragma unroll
    for (int r = 0; r < 4; r++) {
        float inv = 1.0f / l_[r];
        int t = qi0 + ty*4 + r;
        float* orow = &O[((size_t)(b*SEQ + t))*EMB + h*HD];
        float2 o0, o1;
        o0.x = o_[r][0].x*inv; o0.y = o_[r][0].y*inv;
        o1.x = o_[r][1].x*inv; o1.y = o_[r][1].y*inv;
        *(float2*)&orow[2*tx]      = o0;
        *(float2*)&orow[2*tx + 32] = o1;
    }
}

// ------------------------- launch -----------------------------------
extern "C" void kernel_launch(void* const* d_in, const int* in_sizes, int n_in,
                              void* d_out, int out_size)
{
    const float* x     = (const float*)d_in[0];
    const float* ln1_g = (const float*)d_in[2];
    const float* ln1_b = (const float*)d_in[3];
    const float* ln2_g = (const float*)d_in[4];
    const float* ln2_b = (const float*)d_in[5];
    const float* Wq = (const float*)d_in[6];
    const float* bq = (const float*)d_in[7];
    const float* Wk = (const float*)d_in[8];
    const float* bk = (const float*)d_in[9];
    const float* Wv = (const float*)d_in[10];
    const float* bv = (const float*)d_in[11];
    const float* Wo = (const float*)d_in[12];
    const float* bo = (const float*)d_in[13];
    const float* W1 = (const float*)d_in[14];
    const float* b1 = (const float*)d_in[15];
    const float* W2 = (const float*)d_in[16];
    const float* b2 = (const float*)d_in[17];

    float *xn, *q, *k, *v, *att, *x2, *h2, *hf;
    cudaGetSymbolAddress((void**)&xn,  g_xn);
    cudaGetSymbolAddress((void**)&q,   g_q);
    cudaGetSymbolAddress((void**)&k,   g_k);
    cudaGetSymbolAddress((void**)&v,   g_v);
    cudaGetSymbolAddress((void**)&att, g_att);
    cudaGetSymbolAddress((void**)&x2,  g_x2);
    cudaGetSymbolAddress((void**)&h2,  g_h2);
    cudaGetSymbolAddress((void**)&hf,  g_hf);

    const int ATT_SMEM = 4*64*PAD*sizeof(float); // 69632 B
    cudaFuncSetAttribute(attn_kernel, cudaFuncAttributeMaxDynamicSharedMemorySize, ATT_SMEM);

    // ln1
    ln_kernel<<<NTOK, 256>>>(x, ln1_g, ln1_b, xn);
    // QKV projections -> [B,H,T,D]
    gemm_kernel<0><<<dim3(EMB/128, NTOK/128), 256>>>(xn, Wq, bq, nullptr, q, NTOK, EMB, EMB);
    gemm_kernel<0><<<dim3(EMB/128, NTOK/128), 256>>>(xn, Wk, bk, nullptr, k, NTOK, EMB, EMB);
    gemm_kernel<0><<<dim3(EMB/128, NTOK/128), 256>>>(xn, Wv, bv, nullptr, v, NTOK, EMB, EMB);
    // attention
    attn_kernel<<<dim3(SEQ/64, HEADS, BATCH), 256, ATT_SMEM>>>(q, k, v, att);
    // output projection + residual (residual = ln1 output per reference)
    gemm_kernel<1><<<dim3(EMB/128, NTOK/128), 256>>>(att, Wo, bo, xn, x2, NTOK, EMB, EMB);
    // ln2
    ln_kernel<<<NTOK, 256>>>(x2, ln2_g, ln2_b, h2);
    // FFN
    gemm_kernel<2><<<dim3(FFNDIM/128, NTOK/128), 256>>>(h2, W1, b1, nullptr, hf, NTOK, FFNDIM, EMB);
    gemm_kernel<1><<<dim3(EMB/128, NTOK/128), 256>>>(hf, W2, b2, x2, (float*)d_out, NTOK, EMB, FFNDIM);
}

// round 7
// speedup vs baseline: 1.2813x; 1.0216x over previous
#include <cuda_runtime.h>
#include <math.h>

#define EMB   1024
#define HEADS 16
#define HD    64
#define FFNDIM 4096
#define BATCH 2
#define SEQ   2048
#define NTOK  (BATCH*SEQ)

// -------- scratch (device globals; no allocation APIs allowed) --------
__device__ float g_xn [NTOK*EMB];            // ln1 output (also residual base)
__device__ float g_q  [NTOK*EMB];            // [B,H,T,D]
__device__ float g_k  [NTOK*EMB];
__device__ float g_v  [NTOK*EMB];
__device__ float g_att[NTOK*EMB];            // attention output, token-major [M,C]
__device__ float g_x2 [NTOK*EMB];            // x after attn residual
__device__ float g_h2 [NTOK*EMB];            // ln2 output
__device__ float g_hf [(size_t)NTOK*FFNDIM]; // gelu(h@W1+b1)

// ---------------- packed fp32x2 helpers (Blackwell FFMA2 path) -------
__device__ __forceinline__ void fma2(float2 &d, const float2 &a, const float2 &b) {
    asm("fma.rn.f32x2 %0, %1, %2, %0;"
        : "+l"(reinterpret_cast<unsigned long long&>(d))
        : "l"(reinterpret_cast<const unsigned long long&>(a)),
          "l"(reinterpret_cast<const unsigned long long&>(b)));
}
__device__ __forceinline__ float2 dup2(float x) {
    float2 r;
    asm("mov.b64 %0, {%1, %1};"
        : "=l"(reinterpret_cast<unsigned long long&>(r)) : "f"(x));
    return r;
}

// ------------------------- LayerNorm --------------------------------
__global__ void __launch_bounds__(256) ln_kernel(
    const float* __restrict__ x, const float* __restrict__ g,
    const float* __restrict__ b, float* __restrict__ out)
{
    int row = blockIdx.x;
    const float* xr = x + (size_t)row * EMB;
    int t = threadIdx.x;
    float v[4];
    float s = 0.f, sq = 0.f;
#pragma unroll
    for (int i = 0; i < 4; i++) {
        v[i] = xr[t + i*256];
        s += v[i]; sq += v[i]*v[i];
    }
    __shared__ float red[2][8];
#pragma unroll
    for (int o = 16; o; o >>= 1) {
        s  += __shfl_xor_sync(0xffffffffu, s,  o);
        sq += __shfl_xor_sync(0xffffffffu, sq, o);
    }
    int w = t >> 5;
    if ((t & 31) == 0) { red[0][w] = s; red[1][w] = sq; }
    __syncthreads();
    s = red[0][t & 7]; sq = red[1][t & 7];
#pragma unroll
    for (int o = 4; o; o >>= 1) {
        s  += __shfl_xor_sync(0xffffffffu, s,  o);
        sq += __shfl_xor_sync(0xffffffffu, sq, o);
    }
    float mu   = s * (1.0f/EMB);
    float var  = sq * (1.0f/EMB) - mu*mu;
    float rstd = rsqrtf(var + 1e-5f);
    float* outr = out + (size_t)row * EMB;
#pragma unroll
    for (int i = 0; i < 4; i++) {
        int c = t + i*256;
        outr[c] = (v[i] - mu) * rstd * g[c] + b[c];
    }
}

// ------------------------- SGEMM ------------------------------------
// C[M,N] = epilogue(A[M,K] @ B[K,N] + bias), tiles 128x128x16, 8x8/thread,
// f32x2 packed accumulators, double-buffered smem, one bar per 16-k stage.
// B-fragment: thread (txg=tid&15) owns column pairs {2txg+32c}, c=0..3
// -> conflict-free LDS.64.
// EPI 0: bias, write permuted [B,H,T,D] (for Q/K/V)
// EPI 1: bias + residual (res is [M,N] token-major)
// EPI 2: bias + exact-erf GELU
template<int EPI>
__global__ void __launch_bounds__(256, 2) gemm_kernel(
    const float* __restrict__ A, const float* __restrict__ B,
    const float* __restrict__ bias, const float* __restrict__ res,
    float* __restrict__ C, int M, int N, int K)
{
    __shared__ float As[2][16*132];  // transposed A tile [k][m], pad 132
    __shared__ float Bs[2][16*128];  // [k][n]
    int tid = threadIdx.x;
    int m0 = blockIdx.y * 128, n0 = blockIdx.x * 128;
    int arow = tid >> 1,  acol = (tid & 1) * 8;   // 8 k per thread (2 float4)
    int brow = tid >> 4,  bcol = (tid & 15) * 8;  // 16 rows, 8 cols per thread
    const float* Aptr = A + (size_t)(m0 + arow) * K + acol;
    const float* Bptr = B + (size_t)brow * N + n0 + bcol;
    int rbase = (tid >> 4) * 8;
    int txg   = tid & 15;            // column-group owner

    float2 acc[8][4];
#pragma unroll
    for (int i = 0; i < 8; i++)
#pragma unroll
        for (int j = 0; j < 4; j++) acc[i][j] = make_float2(0.f, 0.f);

    // prologue: stage tile 0
    {
        float4 a0 = *(const float4*)Aptr;
        float4 a1 = *(const float4*)(Aptr + 4);
        float4 b0 = *(const float4*)Bptr;
        float4 b1 = *(const float4*)(Bptr + 4);
#pragma unroll
        for (int c2 = 0; c2 < 4; c2++) {
            As[0][(acol+c2  )*132 + arow] = (&a0.x)[c2];
            As[0][(acol+c2+4)*132 + arow] = (&a1.x)[c2];
        }
        *(float4*)&Bs[0][brow*128 + bcol]     = b0;
        *(float4*)&Bs[0][brow*128 + bcol + 4] = b1;
    }
    __syncthreads();

    int ktiles = K >> 4;
    int cur = 0;
    for (int t = 0; t < ktiles; t++) {
        float4 pa0, pa1, pb0, pb1;
        bool more = (t + 1 < ktiles);
        if (more) {
            Aptr += 16;
            Bptr += (size_t)16 * N;
            pa0 = *(const float4*)Aptr;
            pa1 = *(const float4*)(Aptr + 4);
            pb0 = *(const float4*)Bptr;
            pb1 = *(const float4*)(Bptr + 4);
        }
#pragma unroll
        for (int kk = 0; kk < 16; kk++) {
            float4 a0 = *(float4*)&As[cur][kk*132 + rbase];
            float4 a1 = *(float4*)&As[cur][kk*132 + rbase + 4];
            float2 b0 = *(float2*)&Bs[cur][kk*128 + 2*txg];
            float2 b1 = *(float2*)&Bs[cur][kk*128 + 2*txg + 32];
            float2 b2 = *(float2*)&Bs[cur][kk*128 + 2*txg + 64];
            float2 b3 = *(float2*)&Bs[cur][kk*128 + 2*txg + 96];
            float ar[8] = {a0.x,a0.y,a0.z,a0.w,a1.x,a1.y,a1.z,a1.w};
#pragma unroll
            for (int i = 0; i < 8; i++) {
                float2 ad = dup2(ar[i]);
                fma2(acc[i][0], ad, b0);
                fma2(acc[i][1], ad, b1);
                fma2(acc[i][2], ad, b2);
                fma2(acc[i][3], ad, b3);
            }
        }
        if (more) {
            int nxt = cur ^ 1;
#pragma unroll
            for (int c2 = 0; c2 < 4; c2++) {
                As[nxt][(acol+c2  )*132 + arow] = (&pa0.x)[c2];
                As[nxt][(acol+c2+4)*132 + arow] = (&pa1.x)[c2];
            }
            *(float4*)&Bs[nxt][brow*128 + bcol]     = pb0;
            *(float4*)&Bs[nxt][brow*128 + bcol + 4] = pb1;
            __syncthreads();
            cur = nxt;
        }
    }

#pragma unroll
    for (int i = 0; i < 8; i++) {
        int m = m0 + rbase + i;
#pragma unroll
        for (int c = 0; c < 4; c++) {
            int n = n0 + 2*txg + 32*c;
            float2 val;
            val.x = acc[i][c].x + bias[n+0];
            val.y = acc[i][c].y + bias[n+1];
            if (EPI == 0) {
                int bb = m >> 11, tt = m & (SEQ-1);
                int hh = n >> 6,  dd = n & (HD-1);
                size_t off = (((size_t)(bb*HEADS + hh))*SEQ + tt)*HD + dd;
                *(float2*)&C[off] = val;
            } else if (EPI == 1) {
                const float2 rv = *(const float2*)&res[(size_t)m*N + n];
                val.x += rv.x; val.y += rv.y;
                *(float2*)&C[(size_t)m*N + n] = val;
            } else { // GELU exact (erf)
                val.x = 0.5f*val.x*(1.0f + erff(val.x*0.70710678118654752f));
                val.y = 0.5f*val.y*(1.0f + erff(val.y*0.70710678118654752f));
                *(float2*)&C[(size_t)m*N + n] = val;
            }
        }
    }
}

// ------------------------- Attention --------------------------------
// Flash-style: 64 queries/block, sweep keys in 64-wide tiles, online softmax.
// K/V for the NEXT tile are prefetched into registers during compute so the
// global-load latency overlaps QK/softmax/PV. Fragments {2tx, 2tx+32} are
// conflict-free LDS.64; PAD multiple of 4 keeps vector alignment.
#define PAD 68
__global__ void __launch_bounds__(256) attn_kernel(
    const float* __restrict__ Q, const float* __restrict__ K,
    const float* __restrict__ V, float* __restrict__ O)
{
    extern __shared__ float sm[];
    float* Qs = sm;               // [d][i] transposed, pad
    float* Ks = sm + 64*PAD;      // [d][j] transposed
    float* Vs = sm + 2*64*PAD;    // [c][d]
    float* Ps = sm + 3*64*PAD;    // [c][i] transposed

    int tid = threadIdx.x;
    int tx = tid & 15, ty = tid >> 4;
    int h = blockIdx.y, b = blockIdx.z;
    int qi0 = blockIdx.x * 64;
    const float* qbase = Q + ((size_t)(b*HEADS + h))*SEQ*HD;
    const float* kbase = K + ((size_t)(b*HEADS + h))*SEQ*HD;
    const float* vbase = V + ((size_t)(b*HEADS + h))*SEQ*HD;

    // per-thread K/V gather coordinates (4 chunks)
    int rr[4], dd[4];
#pragma unroll
    for (int l = 0; l < 4; l++) {
        int e = tid + l*256;
        rr[l] = e >> 4;
        dd[l] = (e & 15) * 4;
    }

    // load Q tile, transposed + pre-scaled by 1/sqrt(D)
#pragma unroll
    for (int l = 0; l < 4; l++) {
        float4 qv = *(const float4*)(qbase + (size_t)(qi0 + rr[l])*HD + dd[l]);
        Qs[(dd[l]+0)*PAD + rr[l]] = qv.x * 0.125f;
        Qs[(dd[l]+1)*PAD + rr[l]] = qv.y * 0.125f;
        Qs[(dd[l]+2)*PAD + rr[l]] = qv.z * 0.125f;
        Qs[(dd[l]+3)*PAD + rr[l]] = qv.w * 0.125f;
    }

    float m_[4], l_[4];
    float2 o_[4][2];
#pragma unroll
    for (int r = 0; r < 4; r++) {
        m_[r] = -1e30f; l_[r] = 0.f;
        o_[r][0] = make_float2(0.f, 0.f);
        o_[r][1] = make_float2(0.f, 0.f);
    }

    // prologue: prefetch tile 0 into registers
    float4 kpre[4], vpre[4];
#pragma unroll
    for (int l = 0; l < 4; l++) {
        kpre[l] = *(const float4*)(kbase + (size_t)rr[l]*HD + dd[l]);
        vpre[l] = *(const float4*)(vbase + (size_t)rr[l]*HD + dd[l]);
    }

    for (int s0 = 0; s0 < SEQ; s0 += 64) {
        __syncthreads();   // prior PV done reading Ks/Vs/Ps
#pragma unroll
        for (int l = 0; l < 4; l++) {
            Ks[(dd[l]+0)*PAD + rr[l]] = kpre[l].x;
            Ks[(dd[l]+1)*PAD + rr[l]] = kpre[l].y;
            Ks[(dd[l]+2)*PAD + rr[l]] = kpre[l].z;
            Ks[(dd[l]+3)*PAD + rr[l]] = kpre[l].w;
            *(float4*)&Vs[rr[l]*PAD + dd[l]] = vpre[l];
        }
        __syncthreads();

        // prefetch NEXT tile while computing this one
        if (s0 + 64 < SEQ) {
            const float* kn = kbase + (size_t)(s0 + 64)*HD;
            const float* vn = vbase + (size_t)(s0 + 64)*HD;
#pragma unroll
            for (int l = 0; l < 4; l++) {
                kpre[l] = *(const float4*)(kn + (size_t)rr[l]*HD + dd[l]);
                vpre[l] = *(const float4*)(vn + (size_t)rr[l]*HD + dd[l]);
            }
        }

        // S = Q Kt  (keys {2tx,2tx+1} and {2tx+32,2tx+33} per thread)
        float2 s2[4][2];
#pragma unroll
        for (int i = 0; i < 4; i++) {
            s2[i][0] = make_float2(0.f, 0.f);
            s2[i][1] = make_float2(0.f, 0.f);
        }
#pragma unroll 16
        for (int kk = 0; kk < 64; kk++) {
            float4 qv = *(float4*)&Qs[kk*PAD + ty*4];
            float2 k0 = *(float2*)&Ks[kk*PAD + 2*tx];
            float2 k1 = *(float2*)&Ks[kk*PAD + 2*tx + 32];
            float qa[4] = {qv.x,qv.y,qv.z,qv.w};
#pragma unroll
            for (int i = 0; i < 4; i++) {
                float2 qd = dup2(qa[i]);
                fma2(s2[i][0], qd, k0);
                fma2(s2[i][1], qd, k1);
            }
        }

        // online softmax per query row (rows owned by ty group, reduce over tx)
#pragma unroll
        for (int r = 0; r < 4; r++) {
            float sv[4] = {s2[r][0].x, s2[r][0].y, s2[r][1].x, s2[r][1].y};
            float mx = fmaxf(fmaxf(sv[0], sv[1]), fmaxf(sv[2], sv[3]));
#pragma unroll
            for (int o2 = 8; o2; o2 >>= 1)
                mx = fmaxf(mx, __shfl_xor_sync(0xffffffffu, mx, o2, 16));
            float nm = fmaxf(m_[r], mx);
            float cf = __expf(m_[r] - nm);
            float p[4], ps = 0.f;
#pragma unroll
            for (int c = 0; c < 4; c++) { p[c] = __expf(sv[c] - nm); ps += p[c]; }
#pragma unroll
            for (int o2 = 8; o2; o2 >>= 1)
                ps += __shfl_xor_sync(0xffffffffu, ps, o2, 16);
            l_[r] = l_[r]*cf + ps;
            m_[r] = nm;
            o_[r][0].x *= cf; o_[r][0].y *= cf;
            o_[r][1].x *= cf; o_[r][1].y *= cf;
#pragma unroll
            for (int c = 0; c < 4; c++) {
                int j = 2*tx + (c & 1) + (c >> 1)*32;
                Ps[j*PAD + ty*4 + r] = p[c];
            }
        }
        __syncthreads();

        // O += P V  (inner dim = 64 keys; headdim pairs {2tx},{2tx+32})
#pragma unroll 16
        for (int c = 0; c < 64; c++) {
            float4 pv = *(float4*)&Ps[c*PAD + ty*4];
            float2 v0 = *(float2*)&Vs[c*PAD + 2*tx];
            float2 v1 = *(float2*)&Vs[c*PAD + 2*tx + 32];
            float pa[4] = {pv.x,pv.y,pv.z,pv.w};
#pragma unroll
            for (int i = 0; i < 4; i++) {
                float2 pd = dup2(pa[i]);
                fma2(o_[i][0], pd, v0);
                fma2(o_[i][1], pd, v1);
            }
        }
    }

    // finalize + write token-major [M, C]; cols {2tx, 2tx+32} pairs
#pragma unroll
    for (int r = 0; r < 4; r++) {
        float inv = 1.0f / l_[r];
        int t = qi0 + ty*4 + r;
        float* orow = &O[((size_t)(b*SEQ + t))*EMB + h*HD];
        float2 o0, o1;
        o0.x = o_[r][0].x*inv; o0.y = o_[r][0].y*inv;
        o1.x = o_[r][1].x*inv; o1.y = o_[r][1].y*inv;
        *(float2*)&orow[2*tx]      = o0;
        *(float2*)&orow[2*tx + 32] = o1;
    }
}

// ------------------------- launch -----------------------------------
extern "C" void kernel_launch(void* const* d_in, const int* in_sizes, int n_in,
                              void* d_out, int out_size)
{
    const float* x     = (const float*)d_in[0];
    const float* ln1_g = (const float*)d_in[2];
    const float* ln1_b = (const float*)d_in[3];
    const float* ln2_g = (const float*)d_in[4];
    const float* ln2_b = (const float*)d_in[5];
    const float* Wq = (const float*)d_in[6];
    const float* bq = (const float*)d_in[7];
    const float* Wk = (const float*)d_in[8];
    const float* bk = (const float*)d_in[9];
    const float* Wv = (const float*)d_in[10];
    const float* bv = (const float*)d_in[11];
    const float* Wo = (const float*)d_in[12];
    const float* bo = (const float*)d_in[13];
    const float* W1 = (const float*)d_in[14];
    const float* b1 = (const float*)d_in[15];
    const float* W2 = (const float*)d_in[16];
    const float* b2 = (const float*)d_in[17];

    float *xn, *q, *k, *v, *att, *x2, *h2, *hf;
    cudaGetSymbolAddress((void**)&xn,  g_xn);
    cudaGetSymbolAddress((void**)&q,   g_q);
    cudaGetSymbolAddress((void**)&k,   g_k);
    cudaGetSymbolAddress((void**)&v,   g_v);
    cudaGetSymbolAddress((void**)&att, g_att);
    cudaGetSymbolAddress((void**)&x2,  g_x2);
    cudaGetSymbolAddress((void**)&h2,  g_h2);
    cudaGetSymbolAddress((void**)&hf,  g_hf);

    const int ATT_SMEM = 4*64*PAD*sizeof(float); // 69632 B
    cudaFuncSetAttribute(attn_kernel, cudaFuncAttributeMaxDynamicSharedMemorySize, ATT_SMEM);

    // ln1
    ln_kernel<<<NTOK, 256>>>(x, ln1_g, ln1_b, xn);
    // QKV projections -> [B,H,T,D]
    gemm_kernel<0><<<dim3(EMB/128, NTOK/128), 256>>>(xn, Wq, bq, nullptr, q, NTOK, EMB, EMB);
    gemm_kernel<0><<<dim3(EMB/128, NTOK/128), 256>>>(xn, Wk, bk, nullptr, k, NTOK, EMB, EMB);
    gemm_kernel<0><<<dim3(EMB/128, NTOK/128), 256>>>(xn, Wv, bv, nullptr, v, NTOK, EMB, EMB);
    // attention
    attn_kernel<<<dim3(SEQ/64, HEADS, BATCH), 256, ATT_SMEM>>>(q, k, v, att);
    // output projection + residual (residual = ln1 output per reference)
    gemm_kernel<1><<<dim3(EMB/128, NTOK/128), 256>>>(att, Wo, bo, xn, x2, NTOK, EMB, EMB);
    // ln2
    ln_kernel<<<NTOK, 256>>>(x2, ln2_g, ln2_b, h2);
    // FFN
    gemm_kernel<2><<<dim3(FFNDIM/128, NTOK/128), 256>>>(h2, W1, b1, nullptr, hf, NTOK, FFNDIM, EMB);
    gemm_kernel<1><<<dim3(EMB/128, NTOK/128), 256>>>(hf, W2, b2, x2, (float*)d_out, NTOK, EMB, FFNDIM);
}

// round 14
// speedup vs baseline: 1.6270x; 1.2699x over previous
#include <cuda_runtime.h>
#include <cuda_bf16.h>
#include <stdint.h>
#include <math.h>

#define EMB   1024
#define HEADS 16
#define HD    64
#define FFNDIM 4096
#define BATCH 2
#define SEQ   2048
#define NTOK  (BATCH*SEQ)

// -------- scratch (device globals; no allocation APIs allowed) --------
__device__ float g_xn [NTOK*EMB];
__device__ float g_q  [NTOK*EMB];
__device__ float g_k  [NTOK*EMB];
__device__ float g_v  [NTOK*EMB];
__device__ float g_att[NTOK*EMB];
__device__ float g_x2 [NTOK*EMB];
__device__ float g_h2 [NTOK*EMB];
__device__ float g_hf [(size_t)NTOK*FFNDIM];
// bf16 hi/lo staging
__device__ __nv_bfloat16 g_ah[(size_t)NTOK*FFNDIM];
__device__ __nv_bfloat16 g_al[(size_t)NTOK*FFNDIM];
__device__ __nv_bfloat16 g_bh[(size_t)FFNDIM*EMB];
__device__ __nv_bfloat16 g_bl[(size_t)FFNDIM*EMB];

// ---------------- packed fp32x2 helpers (attention) ------------------
__device__ __forceinline__ void fma2(float2 &d, const float2 &a, const float2 &b) {
    asm("fma.rn.f32x2 %0, %1, %2, %0;"
        : "+l"(reinterpret_cast<unsigned long long&>(d))
        : "l"(reinterpret_cast<const unsigned long long&>(a)),
          "l"(reinterpret_cast<const unsigned long long&>(b)));
}
__device__ __forceinline__ float2 dup2(float x) {
    float2 r;
    asm("mov.b64 %0, {%1, %1};"
        : "=l"(reinterpret_cast<unsigned long long&>(r)) : "f"(x));
    return r;
}

// ---------------- mma.sync helpers (base compute_103-legal) ----------
__device__ __forceinline__ uint32_t smem_u32(const void* p) {
    uint32_t a;
    asm("{ .reg .u64 t; cvta.to.shared.u64 t, %1; cvt.u32.u64 %0, t; }"
        : "=r"(a) : "l"(p));
    return a;
}
__device__ __forceinline__ void ldsm_x4(uint32_t &r0, uint32_t &r1, uint32_t &r2,
                                        uint32_t &r3, uint32_t addr) {
    asm volatile("ldmatrix.sync.aligned.m8n8.x4.shared.b16 {%0,%1,%2,%3}, [%4];"
                 : "=r"(r0), "=r"(r1), "=r"(r2), "=r"(r3) : "r"(addr));
}
__device__ __forceinline__ void ldsm_x2(uint32_t &r0, uint32_t &r1, uint32_t addr) {
    asm volatile("ldmatrix.sync.aligned.m8n8.x2.shared.b16 {%0,%1}, [%2];"
                 : "=r"(r0), "=r"(r1) : "r"(addr));
}
__device__ __forceinline__ void mma_bf16(float* c, const uint32_t* a, const uint32_t* b) {
    asm volatile("mma.sync.aligned.m16n8k16.row.col.f32.bf16.bf16.f32 "
                 "{%0,%1,%2,%3}, {%4,%5,%6,%7}, {%8,%9}, {%0,%1,%2,%3};"
                 : "+f"(c[0]), "+f"(c[1]), "+f"(c[2]), "+f"(c[3])
                 : "r"(a[0]), "r"(a[1]), "r"(a[2]), "r"(a[3]), "r"(b[0]), "r"(b[1]));
}

// ------------------------- LayerNorm --------------------------------
__global__ void __launch_bounds__(256) ln_kernel(
    const float* __restrict__ x, const float* __restrict__ g,
    const float* __restrict__ b, float* __restrict__ out)
{
    int row = blockIdx.x;
    const float* xr = x + (size_t)row * EMB;
    int t = threadIdx.x;
    float v[4];
    float s = 0.f, sq = 0.f;
#pragma unroll
    for (int i = 0; i < 4; i++) {
        v[i] = xr[t + i*256];
        s += v[i]; sq += v[i]*v[i];
    }
    __shared__ float red[2][8];
#pragma unroll
    for (int o = 16; o; o >>= 1) {
        s  += __shfl_xor_sync(0xffffffffu, s,  o);
        sq += __shfl_xor_sync(0xffffffffu, sq, o);
    }
    int w = t >> 5;
    if ((t & 31) == 0) { red[0][w] = s; red[1][w] = sq; }
    __syncthreads();
    s = red[0][t & 7]; sq = red[1][t & 7];
#pragma unroll
    for (int o = 4; o; o >>= 1) {
        s  += __shfl_xor_sync(0xffffffffu, s,  o);
        sq += __shfl_xor_sync(0xffffffffu, sq, o);
    }
    float mu   = s * (1.0f/EMB);
    float var  = sq * (1.0f/EMB) - mu*mu;
    float rstd = rsqrtf(var + 1e-5f);
    float* outr = out + (size_t)row * EMB;
#pragma unroll
    for (int i = 0; i < 4; i++) {
        int c = t + i*256;
        outr[c] = (v[i] - mu) * rstd * g[c] + b[c];
    }
}

// --------------- fp32 -> bf16 hi/lo split (same layout) --------------
__global__ void __launch_bounds__(256) split_kernel(
    const float* __restrict__ in, __nv_bfloat16* __restrict__ oh,
    __nv_bfloat16* __restrict__ ol)
{
    size_t i = ((size_t)blockIdx.x * 256 + threadIdx.x) * 4;
    float4 x = *(const float4*)(in + i);
    __nv_bfloat16 h0 = __float2bfloat16(x.x), h1 = __float2bfloat16(x.y);
    __nv_bfloat16 h2 = __float2bfloat16(x.z), h3 = __float2bfloat16(x.w);
    __nv_bfloat16 l0 = __float2bfloat16(x.x - __bfloat162float(h0));
    __nv_bfloat16 l1 = __float2bfloat16(x.y - __bfloat162float(h1));
    __nv_bfloat16 l2 = __float2bfloat16(x.z - __bfloat162float(h2));
    __nv_bfloat16 l3 = __float2bfloat16(x.w - __bfloat162float(h3));
    *(__nv_bfloat162*)(oh + i)     = __nv_bfloat162(h0, h1);
    *(__nv_bfloat162*)(oh + i + 2) = __nv_bfloat162(h2, h3);
    *(__nv_bfloat162*)(ol + i)     = __nv_bfloat162(l0, l1);
    *(__nv_bfloat162*)(ol + i + 2) = __nv_bfloat162(l2, l3);
}

// --------- fp32 [R,C] -> bf16 hi/lo transposed [C,R] -----------------
__global__ void __launch_bounds__(256) tsplit_kernel(
    const float* __restrict__ in, __nv_bfloat16* __restrict__ oh,
    __nv_bfloat16* __restrict__ ol, int R, int C)
{
    __shared__ float ts[32][33];
    int x0 = blockIdx.x * 32, y0 = blockIdx.y * 32;
    int tx = threadIdx.x & 31, ty = threadIdx.x >> 5;
#pragma unroll
    for (int i = 0; i < 4; i++)
        ts[ty + 8*i][tx] = in[(size_t)(y0 + ty + 8*i) * C + x0 + tx];
    __syncthreads();
#pragma unroll
    for (int i = 0; i < 4; i++) {
        float v = ts[tx][ty + 8*i];
        __nv_bfloat16 h = __float2bfloat16(v);
        __nv_bfloat16 l = __float2bfloat16(v - __bfloat162float(h));
        size_t off = (size_t)(x0 + ty + 8*i) * R + y0 + tx;
        oh[off] = h;
        ol[off] = l;
    }
}

// ---------------- bf16x3 warp-MMA GEMM -------------------------------
// C[M,N] = epi(A@B + bias). A hi/lo [M,K] K-major; B hi/lo [N,K] K-major.
// CTA tile 128x128x32; 8 warps as 4(M) x 2(N); warp tile 32x64.
// Per (mt,nt,ks): 3 mma.m16n8k16 (AhBh, AhBl, AlBh) into fp32 acc.
// Smem rows padded to 40 bf16 (80B) -> conflict-free ldmatrix.
// EPI 0: bias + permuted [B,H,T,D]; 1: bias+residual; 2: bias+GELU(erf).
#define WG_STRIDE 40
template<int EPI>
__global__ void __launch_bounds__(256, 2) wgemm_kernel(
    const __nv_bfloat16* __restrict__ Ah, const __nv_bfloat16* __restrict__ Al,
    const __nv_bfloat16* __restrict__ Bh, const __nv_bfloat16* __restrict__ Bl,
    const float* __restrict__ bias, const float* __restrict__ res,
    float* __restrict__ C, int M, int N, int K)
{
    __shared__ __align__(16) __nv_bfloat16 sAh[128*WG_STRIDE];
    __shared__ __align__(16) __nv_bfloat16 sAl[128*WG_STRIDE];
    __shared__ __align__(16) __nv_bfloat16 sBh[128*WG_STRIDE];
    __shared__ __align__(16) __nv_bfloat16 sBl[128*WG_STRIDE];

    int tid  = threadIdx.x;
    int lane = tid & 31, wid = tid >> 5;
    int wr = wid & 3, wc = wid >> 2;           // warp 4(M) x 2(N)
    int m0 = blockIdx.y * 128, n0 = blockIdx.x * 128;

    // gmem->smem mapping: thread loads 32B (2x uint4) per matrix per tile
    int grow = tid >> 1, ghalf = tid & 1;      // row 0..127, k-half 0/1
    const __nv_bfloat16* pAh = Ah + (size_t)(m0 + grow) * K + ghalf * 16;
    const __nv_bfloat16* pAl = Al + (size_t)(m0 + grow) * K + ghalf * 16;
    const __nv_bfloat16* pBh = Bh + (size_t)(n0 + grow) * K + ghalf * 16;
    const __nv_bfloat16* pBl = Bl + (size_t)(n0 + grow) * K + ghalf * 16;
    int soff = grow * WG_STRIDE + ghalf * 16;

    uint32_t aAh = smem_u32(sAh), aAl = smem_u32(sAl);
    uint32_t aBh = smem_u32(sBh), aBl = smem_u32(sBl);

    // ldmatrix lane addressing
    int a_row  = wr * 32 + (lane & 15);
    uint32_t a_koff = (uint32_t)(lane >> 4) * 16;
    int b_row  = wc * 64 + (lane & 7);
    uint32_t b_koff = (uint32_t)((lane >> 3) & 1) * 16;

    float acc[2][8][4];
#pragma unroll
    for (int mt = 0; mt < 2; mt++)
#pragma unroll
        for (int nt = 0; nt < 8; nt++)
#pragma unroll
            for (int i = 0; i < 4; i++) acc[mt][nt][i] = 0.f;

    int NT = K >> 5;
    for (int t = 0; t < NT; t++) {
        int k0 = t << 5;
        uint4 vah0 = *(const uint4*)(pAh + k0);
        uint4 vah1 = *(const uint4*)(pAh + k0 + 8);
        uint4 val0 = *(const uint4*)(pAl + k0);
        uint4 val1 = *(const uint4*)(pAl + k0 + 8);
        uint4 vbh0 = *(const uint4*)(pBh + k0);
        uint4 vbh1 = *(const uint4*)(pBh + k0 + 8);
        uint4 vbl0 = *(const uint4*)(pBl + k0);
        uint4 vbl1 = *(const uint4*)(pBl + k0 + 8);
        *(uint4*)&sAh[soff]     = vah0;
        *(uint4*)&sAh[soff + 8] = vah1;
        *(uint4*)&sAl[soff]     = val0;
        *(uint4*)&sAl[soff + 8] = val1;
        *(uint4*)&sBh[soff]     = vbh0;
        *(uint4*)&sBh[soff + 8] = vbh1;
        *(uint4*)&sBl[soff]     = vbl0;
        *(uint4*)&sBl[soff + 8] = vbl1;
        __syncthreads();

#pragma unroll
        for (int ks = 0; ks < 2; ks++) {
            uint32_t kb = ks * 32;
            uint32_t ah[2][4], al[2][4];
#pragma unroll
            for (int mt = 0; mt < 2; mt++) {
                uint32_t ra = (uint32_t)(a_row + mt*16) * 80 + kb + a_koff;
                ldsm_x4(ah[mt][0], ah[mt][1], ah[mt][2], ah[mt][3], aAh + ra);
                ldsm_x4(al[mt][0], al[mt][1], al[mt][2], al[mt][3], aAl + ra);
            }
#pragma unroll
            for (int nt = 0; nt < 8; nt++) {
                uint32_t rb = (uint32_t)(b_row + nt*8) * 80 + kb + b_koff;
                uint32_t bh[2], bl[2];
                ldsm_x2(bh[0], bh[1], aBh + rb);
                ldsm_x2(bl[0], bl[1], aBl + rb);
#pragma unroll
                for (int mt = 0; mt < 2; mt++) {
                    mma_bf16(acc[mt][nt], ah[mt], bh);
                    mma_bf16(acc[mt][nt], ah[mt], bl);
                    mma_bf16(acc[mt][nt], al[mt], bh);
                }
            }
        }
        __syncthreads();
    }

    // epilogue: lane T holds rows {q, q+8}, cols {2p, 2p+1} per frag
    int q = lane >> 2, p = lane & 3;
#pragma unroll
    for (int mt = 0; mt < 2; mt++) {
#pragma unroll
        for (int nt = 0; nt < 8; nt++) {
            int col = n0 + wc*64 + nt*8 + 2*p;
            float bx = __ldg(&bias[col]), by = __ldg(&bias[col+1]);
#pragma unroll
            for (int half = 0; half < 2; half++) {
                int m = m0 + wr*32 + mt*16 + q + half*8;
                float2 v;
                v.x = acc[mt][nt][2*half+0] + bx;
                v.y = acc[mt][nt][2*half+1] + by;
                if (EPI == 0) {
                    int bb = m >> 11, tt = m & (SEQ-1);
                    int hh = col >> 6, dd = col & (HD-1);
                    *(float2*)&C[(((size_t)(bb*HEADS + hh))*SEQ + tt)*HD + dd] = v;
                } else if (EPI == 1) {
                    const float2 rv = *(const float2*)&res[(size_t)m*N + col];
                    v.x += rv.x; v.y += rv.y;
                    *(float2*)&C[(size_t)m*N + col] = v;
                } else {
                    v.x = 0.5f*v.x*(1.0f + erff(v.x*0.70710678118654752f));
                    v.y = 0.5f*v.y*(1.0f + erff(v.y*0.70710678118654752f));
                    *(float2*)&C[(size_t)m*N + col] = v;
                }
            }
        }
    }
}

// ------------------------- Attention (round-7 version) ---------------
#define PAD 68
__global__ void __launch_bounds__(256) attn_kernel(
    const float* __restrict__ Q, const float* __restrict__ K,
    const float* __restrict__ V, float* __restrict__ O)
{
    extern __shared__ float sm[];
    float* Qs = sm;
    float* Ks = sm + 64*PAD;
    float* Vs = sm + 2*64*PAD;
    float* Ps = sm + 3*64*PAD;

    int tid = threadIdx.x;
    int tx = tid & 15, ty = tid >> 4;
    int h = blockIdx.y, b = blockIdx.z;
    int qi0 = blockIdx.x * 64;
    const float* qbase = Q + ((size_t)(b*HEADS + h))*SEQ*HD;
    const float* kbase = K + ((size_t)(b*HEADS + h))*SEQ*HD;
    const float* vbase = V + ((size_t)(b*HEADS + h))*SEQ*HD;

    int rr[4], dd[4];
#pragma unroll
    for (int l = 0; l < 4; l++) {
        int e = tid + l*256;
        rr[l] = e >> 4;
        dd[l] = (e & 15) * 4;
    }

#pragma unroll
    for (int l = 0; l < 4; l++) {
        float4 qv = *(const float4*)(qbase + (size_t)(qi0 + rr[l])*HD + dd[l]);
        Qs[(dd[l]+0)*PAD + rr[l]] = qv.x * 0.125f;
        Qs[(dd[l]+1)*PAD + rr[l]] = qv.y * 0.125f;
        Qs[(dd[l]+2)*PAD + rr[l]] = qv.z * 0.125f;
        Qs[(dd[l]+3)*PAD + rr[l]] = qv.w * 0.125f;
    }

    float m_[4], l_[4];
    float2 o_[4][2];
#pragma unroll
    for (int r = 0; r < 4; r++) {
        m_[r] = -1e30f; l_[r] = 0.f;
        o_[r][0] = make_float2(0.f, 0.f);
        o_[r][1] = make_float2(0.f, 0.f);
    }

    float4 kpre[4], vpre[4];
#pragma unroll
    for (int l = 0; l < 4; l++) {
        kpre[l] = *(const float4*)(kbase + (size_t)rr[l]*HD + dd[l]);
        vpre[l] = *(const float4*)(vbase + (size_t)rr[l]*HD + dd[l]);
    }

    for (int s0 = 0; s0 < SEQ; s0 += 64) {
        __syncthreads();
#pragma unroll
        for (int l = 0; l < 4; l++) {
            Ks[(dd[l]+0)*PAD + rr[l]] = kpre[l].x;
            Ks[(dd[l]+1)*PAD + rr[l]] = kpre[l].y;
            Ks[(dd[l]+2)*PAD + rr[l]] = kpre[l].z;
            Ks[(dd[l]+3)*PAD + rr[l]] = kpre[l].w;
            *(float4*)&Vs[rr[l]*PAD + dd[l]] = vpre[l];
        }
        __syncthreads();

        if (s0 + 64 < SEQ) {
            const float* kn = kbase + (size_t)(s0 + 64)*HD;
            const float* vn = vbase + (size_t)(s0 + 64)*HD;
#pragma unroll
            for (int l = 0; l < 4; l++) {
                kpre[l] = *(const float4*)(kn + (size_t)rr[l]*HD + dd[l]);
                vpre[l] = *(const float4*)(vn + (size_t)rr[l]*HD + dd[l]);
            }
        }

        float2 s2[4][2];
#pragma unroll
        for (int i = 0; i < 4; i++) {
            s2[i][0] = make_float2(0.f, 0.f);
            s2[i][1] = make_float2(0.f, 0.f);
        }
#pragma unroll 16
        for (int kk = 0; kk < 64; kk++) {
            float4 qv = *(float4*)&Qs[kk*PAD + ty*4];
            float2 k0 = *(float2*)&Ks[kk*PAD + 2*tx];
            float2 k1 = *(float2*)&Ks[kk*PAD + 2*tx + 32];
            float qa[4] = {qv.x,qv.y,qv.z,qv.w};
#pragma unroll
            for (int i = 0; i < 4; i++) {
                float2 qd = dup2(qa[i]);
                fma2(s2[i][0], qd, k0);
                fma2(s2[i][1], qd, k1);
            }
        }

#pragma unroll
        for (int r = 0; r < 4; r++) {
            float sv[4] = {s2[r][0].x, s2[r][0].y, s2[r][1].x, s2[r][1].y};
            float mx = fmaxf(fmaxf(sv[0], sv[1]), fmaxf(sv[2], sv[3]));
#pragma unroll
            for (int o2 = 8; o2; o2 >>= 1)
                mx = fmaxf(mx, __shfl_xor_sync(0xffffffffu, mx, o2, 16));
            float nm = fmaxf(m_[r], mx);
            float cf = __expf(m_[r] - nm);
            float p[4], ps = 0.f;
#pragma unroll
            for (int c = 0; c < 4; c++) { p[c] = __expf(sv[c] - nm); ps += p[c]; }
#pragma unroll
            for (int o2 = 8; o2; o2 >>= 1)
                ps += __shfl_xor_sync(0xffffffffu, ps, o2, 16);
            l_[r] = l_[r]*cf + ps;
            m_[r] = nm;
            o_[r][0].x *= cf; o_[r][0].y *= cf;
            o_[r][1].x *= cf; o_[r][1].y *= cf;
#pragma unroll
            for (int c = 0; c < 4; c++) {
                int j = 2*tx + (c & 1) + (c >> 1)*32;
                Ps[j*PAD + ty*4 + r] = p[c];
            }
        }
        __syncthreads();

#pragma unroll 16
        for (int c = 0; c < 64; c++) {
            float4 pv = *(float4*)&Ps[c*PAD + ty*4];
            float2 v0 = *(float2*)&Vs[c*PAD + 2*tx];
            float2 v1 = *(float2*)&Vs[c*PAD + 2*tx + 32];
            float pa[4] = {pv.x,pv.y,pv.z,pv.w};
#pragma unroll
            for (int i = 0; i < 4; i++) {
                float2 pd = dup2(pa[i]);
                fma2(o_[i][0], pd, v0);
                fma2(o_[i][1], pd, v1);
            }
        }
    }

#pragma unroll
    for (int r = 0; r < 4; r++) {
        float inv = 1.0f / l_[r];
        int t = qi0 + ty*4 + r;
        float* orow = &O[((size_t)(b*SEQ + t))*EMB + h*HD];
        float2 o0, o1;
        o0.x = o_[r][0].x*inv; o0.y = o_[r][0].y*inv;
        o1.x = o_[r][1].x*inv; o1.y = o_[r][1].y*inv;
        *(float2*)&orow[2*tx]      = o0;
        *(float2*)&orow[2*tx + 32] = o1;
    }
}

// ------------------------- launch -----------------------------------
extern "C" void kernel_launch(void* const* d_in, const int* in_sizes, int n_in,
                              void* d_out, int out_size)
{
    const float* x     = (const float*)d_in[0];
    const float* ln1_g = (const float*)d_in[2];
    const float* ln1_b = (const float*)d_in[3];
    const float* ln2_g = (const float*)d_in[4];
    const float* ln2_b = (const float*)d_in[5];
    const float* Wq = (const float*)d_in[6];
    const float* bq = (const float*)d_in[7];
    const float* Wk = (const float*)d_in[8];
    const float* bk = (const float*)d_in[9];
    const float* Wv = (const float*)d_in[10];
    const float* bv = (const float*)d_in[11];
    const float* Wo = (const float*)d_in[12];
    const float* bo = (const float*)d_in[13];
    const float* W1 = (const float*)d_in[14];
    const float* b1 = (const float*)d_in[15];
    const float* W2 = (const float*)d_in[16];
    const float* b2 = (const float*)d_in[17];

    float *xn, *q, *k, *v, *att, *x2, *h2, *hf;
    __nv_bfloat16 *ah, *al, *bh, *bl;
    cudaGetSymbolAddress((void**)&xn,  g_xn);
    cudaGetSymbolAddress((void**)&q,   g_q);
    cudaGetSymbolAddress((void**)&k,   g_k);
    cudaGetSymbolAddress((void**)&v,   g_v);
    cudaGetSymbolAddress((void**)&att, g_att);
    cudaGetSymbolAddress((void**)&x2,  g_x2);
    cudaGetSymbolAddress((void**)&h2,  g_h2);
    cudaGetSymbolAddress((void**)&hf,  g_hf);
    cudaGetSymbolAddress((void**)&ah,  g_ah);
    cudaGetSymbolAddress((void**)&al,  g_al);
    cudaGetSymbolAddress((void**)&bh,  g_bh);
    cudaGetSymbolAddress((void**)&bl,  g_bl);

    const int ATT_SMEM = 4*64*PAD*sizeof(float);
    cudaFuncSetAttribute(attn_kernel, cudaFuncAttributeMaxDynamicSharedMemorySize, ATT_SMEM);

    // ln1 + split A (shared by QKV)
    ln_kernel<<<NTOK, 256>>>(x, ln1_g, ln1_b, xn);
    split_kernel<<<NTOK*EMB/1024, 256>>>(xn, ah, al);
    // QKV
    tsplit_kernel<<<dim3(EMB/32, EMB/32), 256>>>(Wq, bh, bl, EMB, EMB);
    wgemm_kernel<0><<<dim3(EMB/128, NTOK/128), 256>>>(ah, al, bh, bl, bq, nullptr, q, NTOK, EMB, EMB);
    tsplit_kernel<<<dim3(EMB/32, EMB/32), 256>>>(Wk, bh, bl, EMB, EMB);
    wgemm_kernel<0><<<dim3(EMB/128, NTOK/128), 256>>>(ah, al, bh, bl, bk, nullptr, k, NTOK, EMB, EMB);
    tsplit_kernel<<<dim3(EMB/32, EMB/32), 256>>>(Wv, bh, bl, EMB, EMB);
    wgemm_kernel<0><<<dim3(EMB/128, NTOK/128), 256>>>(ah, al, bh, bl, bv, nullptr, v, NTOK, EMB, EMB);
    // attention
    attn_kernel<<<dim3(SEQ/64, HEADS, BATCH), 256, ATT_SMEM>>>(q, k, v, att);
    // O projection + residual(ln1 out)
    split_kernel<<<NTOK*EMB/1024, 256>>>(att, ah, al);
    tsplit_kernel<<<dim3(EMB/32, EMB/32), 256>>>(Wo, bh, bl, EMB, EMB);
    wgemm_kernel<1><<<dim3(EMB/128, NTOK/128), 256>>>(ah, al, bh, bl, bo, xn, x2, NTOK, EMB, EMB);
    // ln2 + FFN
    ln_kernel<<<NTOK, 256>>>(x2, ln2_g, ln2_b, h2);
    split_kernel<<<NTOK*EMB/1024, 256>>>(h2, ah, al);
    tsplit_kernel<<<dim3(FFNDIM/32, EMB/32), 256>>>(W1, bh, bl, EMB, FFNDIM);
    wgemm_kernel<2><<<dim3(FFNDIM/128, NTOK/128), 256>>>(ah, al, bh, bl, b1, nullptr, hf, NTOK, FFNDIM, EMB);
    split_kernel<<<(int)((size_t)NTOK*FFNDIM/1024), 256>>>(hf, ah, al);
    tsplit_kernel<<<dim3(EMB/32, FFNDIM/32), 256>>>(W2, bh, bl, FFNDIM, EMB);
    wgemm_kernel<1><<<dim3(EMB/128, NTOK/128), 256>>>(ah, al, bh, bl, b2, x2, (float*)d_out, NTOK, EMB, FFNDIM);
}